// round 8
// baseline (speedup 1.0000x reference)
#include <cuda_runtime.h>
#include <cfloat>
#include <cstdint>

#define R_    512
#define K_    17
#define HIN   56
#define OUT   96
#define NT    192
#define MPC   4
#define NMAP  (R_ * K_)
#define TS    68                   // 68 mod 32 = 4 -> max 2-way bank conflicts
#define PAD   4                    // col c stored at word c+4
#define TROWS 48                   // half of the output rows resident

// ---- compile-time bicubic helpers (period 12 for 56->96) ----
__host__ __device__ constexpr float cubicw_c(float x) {
    x = x < 0.f ? -x : x;
    float nearw = (1.25f * x - 2.25f) * x * x + 1.0f;
    float farw  = -0.75f * (((x - 5.0f) * x + 8.0f) * x - 4.0f);
    return x <= 1.0f ? nearw : farw;
}
__host__ __device__ constexpr float srcf(int t) {
    return ((float)t + 0.5f) * (56.0f / 96.0f) - 0.5f;
}
__host__ __device__ constexpr int ifloorf_c(float x) {
    int i = (int)x;
    return ((float)i > x) ? i - 1 : i;
}
__host__ __device__ constexpr int bofs(int t) { return ifloorf_c(srcf(t)); }
__host__ __device__ constexpr int brel(int T) { return 7 * (T / 12) + bofs(T % 12); }
__host__ __device__ constexpr float wgt(int t, int k) {
    return cubicw_c(srcf(t) - (float)(bofs(t) - 1 + k));
}

struct WTab { float w[12][4]; int b[12]; };
__host__ __device__ constexpr WTab make_wtab() {
    WTab r{};
    for (int t = 0; t < 12; ++t) {
        r.b[t] = bofs(t);
        for (int k = 0; k < 4; ++k) r.w[t][k] = wgt(t, k);
    }
    return r;
}
__constant__ WTab cWT = make_wtab();

// ---- cp.async helpers ----
__device__ __forceinline__ void cp16(unsigned int sdst, const void* gsrc) {
    asm volatile("cp.async.cg.shared.global [%0], [%1], 16;" :: "r"(sdst), "l"(gsrc));
}
__device__ __forceinline__ void cp_commit() { asm volatile("cp.async.commit_group;"); }
__device__ __forceinline__ void cp_wait0() { asm volatile("cp.async.wait_group 0;"); }

__device__ __forceinline__ void prefetch_mask(unsigned int smask_u,
                                              const float* __restrict__ masks,
                                              int map, int tid) {
    const float4* g = (const float4*)(masks + (size_t)map * (HIN * HIN));
    #pragma unroll
    for (int i = 0; i < 4; i++)
        cp16(smask_u + (tid + i * NT) * 16, g + tid + i * NT);
    if (tid < 16)
        cp16(smask_u + (768 + tid) * 16, g + 768 + tid);
}

// clamped float2 row load from the smem-staged mask
__device__ __forceinline__ float2 ldrow2s(const float* __restrict__ sm, int row) {
    row = min(max(row, 0), HIN - 1);
    return *(const float2*)(sm + row * HIN);
}

// ---------------- pass 1: vertical 56->96, float2 column-pair lanes ----------
template<int T>
__device__ __forceinline__ void p1_all(
    float2& m0, float2& m1, float2& m2, float2& m3,
    const float* __restrict__ sm, int g7, float* __restrict__ dst,
    bool isL, bool isR)
{
    if constexpr (T < 12) {
        if constexpr (T == 0) {
            m0 = ldrow2s(sm, g7 + bofs(0) - 1);
            m1 = ldrow2s(sm, g7 + bofs(0)    );
            m2 = ldrow2s(sm, g7 + bofs(0) + 1);
            m3 = ldrow2s(sm, g7 + bofs(0) + 2);
        } else if constexpr (bofs(T) != bofs(T - 1)) {   // advances by <=1
            m0 = m1; m1 = m2; m2 = m3;
            m3 = ldrow2s(sm, g7 + bofs(T) + 2);
        }
        constexpr float W0 = wgt(T, 0), W1 = wgt(T, 1), W2 = wgt(T, 2), W3 = wgt(T, 3);
        float2 v;
        v.x = fmaf(m3.x, W3, fmaf(m2.x, W2, fmaf(m1.x, W1, m0.x * W0)));
        v.y = fmaf(m3.y, W3, fmaf(m2.y, W2, fmaf(m1.y, W1, m0.y * W0)));
        *(float2*)(dst + T * TS) = v;
        if (isL) *(float2*)(dst + T * TS - 2) = make_float2(v.x, v.x); // cols -2,-1
        if (isR) *(float2*)(dst + T * TS + 2) = make_float2(v.y, v.y); // cols 56,57
        p1_all<T + 1>(m0, m1, m2, m3, sm, g7, dst, isL, isR);
    }
}

// ---------------- pass 2: 24-col quarter per thread, OFS = alignment shift ---
template<int C, int HI>
__device__ __forceinline__ void p2chunks(float* __restrict__ row, const float4* __restrict__ src) {
    if constexpr (C <= HI) {
        float4 q = src[C];
        row[4 * C + 0] = q.x; row[4 * C + 1] = q.y;
        row[4 * C + 2] = q.z; row[4 * C + 3] = q.w;
        p2chunks<C + 1, HI>(row, src);
    }
}
template<int T, int OFS>
__device__ __forceinline__ void p2load(float* __restrict__ row, const float4* __restrict__ src) {
    constexpr int hi = (brel(T) + 4 + OFS) / 4;
    constexpr int lo = (T == 0) ? 0 : (brel(T - 1) + 4 + OFS) / 4 + 1;
    p2chunks<lo, hi>(row, src);
}
template<int T, int OFS>
__device__ __forceinline__ float p2v(const float* __restrict__ row) {
    constexpr int   t = T % 12;
    constexpr int   b = brel(T) + 1 + OFS;
    constexpr float W0 = wgt(t, 0), W1 = wgt(t, 1), W2 = wgt(t, 2), W3 = wgt(t, 3);
    return fmaf(row[b + 3], W3, fmaf(row[b + 2], W2, fmaf(row[b + 1], W1, row[b] * W0)));
}
template<int G, int OFS>
__device__ __forceinline__ void p2group(
    float* __restrict__ row, const float4* __restrict__ src,
    float& best, int& bestGS, int baseIdx)
{
    if constexpr (G < 6) {
        p2load<4 * G + 0, OFS>(row, src); float v0 = p2v<4 * G + 0, OFS>(row);
        p2load<4 * G + 1, OFS>(row, src); float v1 = p2v<4 * G + 1, OFS>(row);
        p2load<4 * G + 2, OFS>(row, src); float v2 = p2v<4 * G + 2, OFS>(row);
        p2load<4 * G + 3, OFS>(row, src); float v3 = p2v<4 * G + 3, OFS>(row);
        float gm = fmaxf(fmaxf(v0, v1), fmaxf(v2, v3));
        if (gm > best) { best = gm; bestGS = baseIdx + 4 * G; } // strict '>': earliest group
        p2group<G + 1, OFS>(row, src, best, bestGS, baseIdx);
    }
}

__global__ void __launch_bounds__(NT, 7) kp_kernel(
    const float* __restrict__ masks,
    const float* __restrict__ boxes,
    float* __restrict__ out)
{
    __shared__ float s_mask[HIN * HIN];     // 12.25 KB (cp.async staged)
    __shared__ float s_tmp[TROWS * TS];     // 12.75 KB (one 48-row half)
    __shared__ float s_rv[NT / 32];
    __shared__ int   s_ri[NT / 32];

    const int tid  = threadIdx.x;
    const int map0 = blockIdx.x * MPC;

    unsigned int smask_u = (unsigned int)__cvta_generic_to_shared(s_mask);

    prefetch_mask(smask_u, masks, map0, tid);
    cp_commit();

    for (int m = 0; m < MPC; m++) {
        const int map = map0 + m;
        float candV = -FLT_MAX;
        int   candI = 0;

        cp_wait0();
        __syncthreads();                  // mask ready; s_tmp/s_rv free

        #pragma unroll
        for (int H = 0; H < 2; H++) {
            // ---- pass 1 (half H): 112 threads = (block g, col pair p) ----
            if (tid < 112) {
                int g = tid / 28;          // 0..3
                int p = tid - g * 28;      // 0..27
                const float* sm = s_mask + 2 * p;
                float* dst = s_tmp + (12 * g) * TS + PAD + 2 * p;
                float2 a0, a1, a2, a3;
                p1_all<0>(a0, a1, a2, a3, sm, 7 * (g + 4 * H), dst, p == 0, p == 27);
            }
            __syncthreads();

            // prefetch next map once the mask is fully consumed (after half B's pass 1)
            if (H == 1) {
                if (m + 1 < MPC) prefetch_mask(smask_u, masks, map + 1, tid);
                cp_commit();
            }

            // ---- pass 2 (half H): 192 threads = (local row lh, quarter q) ----
            float best = -FLT_MAX;
            int bestGS = 0x7fffffff;
            {
                int lh = tid >> 2;
                int q  = tid & 3;
                const float* base = s_tmp + lh * TS;
                int baseIdx = (lh + TROWS * H) * OUT + 24 * q;
                float row[20];
                if ((q & 1) == 0)
                    p2group<0, 2>(row, (const float4*)(base + 14 * q), best, bestGS, baseIdx);
                else
                    p2group<0, 0>(row, (const float4*)(base + 14 * q + 2), best, bestGS, baseIdx);
            }

            #pragma unroll
            for (int off = 16; off > 0; off >>= 1) {
                float ov = __shfl_down_sync(0xffffffffu, best, off);
                int   og = __shfl_down_sync(0xffffffffu, bestGS, off);
                if (ov > best || (ov == best && og < bestGS)) { best = ov; bestGS = og; }
            }
            if ((tid & 31) == 0) { s_rv[tid >> 5] = best; s_ri[tid >> 5] = bestGS; }
            __syncthreads();

            if (tid == 0) {
                #pragma unroll
                for (int i = 1; i < NT / 32; i++) {
                    float ov = s_rv[i]; int og = s_ri[i];
                    if (ov > best || (ov == best && og < bestGS)) { best = ov; bestGS = og; }
                }
                // exact within-group index recovery (bit-identical recompute),
                // must run before s_tmp is overwritten by the next half/map
                int gs = bestGS;
                int hh = gs / OUT;
                int w0 = gs - hh * OUT;
                int lr = hh - TROWS * H;
                int found = 0;
                #pragma unroll
                for (int i = 3; i >= 0; i--) {   // descending: final = first match
                    int T = w0 + i;
                    int d = T / 12;
                    int t = T - 12 * d;
                    const float* p = s_tmp + lr * TS + 3 + 7 * d + cWT.b[t];
                    float v = fmaf(p[3], cWT.w[t][3],
                              fmaf(p[2], cWT.w[t][2],
                              fmaf(p[1], cWT.w[t][1], p[0] * cWT.w[t][0])));
                    if (v == best) { found = i; }
                }
                int idx = gs + found;
                // combine halves: half A indices < half B, so strict '>' for B
                if (best > candV) { candV = best; candI = idx; }
            }
            __syncthreads();              // recovery done before s_tmp reuse
        }

        if (tid == 0) {
            int bestIdx = candI;
            float best  = candV;
            int r = map / K_;
            int k = map - r * K_;
            float b0 = boxes[r * 4 + 0];
            float b1 = boxes[r * 4 + 1];
            float b2 = boxes[r * 4 + 2];
            float b3 = boxes[r * 4 + 3];
            float len0 = fmaxf(b2 - b0, 1.0f);
            float len1 = fmaxf(b3 - b1, 1.0f);
            int y = bestIdx / OUT;
            int x = bestIdx - y * OUT;
            float p0 = ((float)y + 0.5f) * (len0 / (float)OUT) + b0;
            float p1 = ((float)x + 0.5f) * (len1 / (float)OUT) + b1;

            float* pred   = out;                    // [R, 3, K]
            float* scores = out + R_ * 3 * K_;      // [R, K]
            pred[r * 3 * K_ + 0 * K_ + k] = p0;
            pred[r * 3 * K_ + 1 * K_ + k] = p1;
            pred[r * 3 * K_ + 2 * K_ + k] = 1.0f;
            scores[r * K_ + k] = best;
        }
    }
}

extern "C" void kernel_launch(void* const* d_in, const int* in_sizes, int n_in,
                              void* d_out, int out_size) {
    const float* masks = (const float*)d_in[0];   // [512,17,56,56] f32
    const float* boxes = (const float*)d_in[1];   // [512,4] f32
    float* out = (float*)d_out;
    kp_kernel<<<NMAP / MPC, NT>>>(masks, boxes, out);
}

// round 9
// speedup vs baseline: 1.5215x; 1.5215x over previous
#include <cuda_runtime.h>
#include <cfloat>
#include <cstdint>

#define R_    512
#define K_    17
#define HIN   56
#define OUT   96
#define NT    192
#define MPC   4                    // maps per CTA
#define NMAP  (R_ * K_)
#define TS    68                   // 68 mod 32 = 4 -> max 2-way LDS.128 conflicts
#define PAD   4                    // col c stored at word c+4

// ---- compile-time bicubic helpers (period 12 for 56->96) ----
__host__ __device__ constexpr float cubicw_c(float x) {
    x = x < 0.f ? -x : x;
    float nearw = (1.25f * x - 2.25f) * x * x + 1.0f;
    float farw  = -0.75f * (((x - 5.0f) * x + 8.0f) * x - 4.0f);
    return x <= 1.0f ? nearw : farw;
}
__host__ __device__ constexpr float srcf(int t) {
    return ((float)t + 0.5f) * (56.0f / 96.0f) - 0.5f;
}
__host__ __device__ constexpr int ifloorf_c(float x) {
    int i = (int)x;
    return ((float)i > x) ? i - 1 : i;
}
__host__ __device__ constexpr int bofs(int t) { return ifloorf_c(srcf(t)); }
__host__ __device__ constexpr int brel(int T) { return 7 * (T / 12) + bofs(T % 12); }
__host__ __device__ constexpr float wgt(int t, int k) {
    return cubicw_c(srcf(t) - (float)(bofs(t) - 1 + k));
}

struct WTab { float w[12][4]; int b[12]; };
__host__ __device__ constexpr WTab make_wtab() {
    WTab r{};
    for (int t = 0; t < 12; ++t) {
        r.b[t] = bofs(t);
        for (int k = 0; k < 4; ++k) r.w[t][k] = wgt(t, k);
    }
    return r;
}
__constant__ WTab cWT = make_wtab();

// ---- cp.async 16B helper ----
__device__ __forceinline__ void cp16(unsigned int sdst, const void* gsrc) {
    asm volatile("cp.async.cg.shared.global [%0], [%1], 16;" :: "r"(sdst), "l"(gsrc));
}
__device__ __forceinline__ void cp_commit() {
    asm volatile("cp.async.commit_group;");
}
__device__ __forceinline__ void cp_wait0() {
    asm volatile("cp.async.wait_group 0;");
}

// clamped row load from the smem-staged mask
__device__ __forceinline__ float4 ldrow4s(const float* __restrict__ sm, int row) {
    row = min(max(row, 0), HIN - 1);
    return *(const float4*)(sm + row * HIN);
}

// ---------------- pass 1: vertical 56->96 from smem mask, float4 lanes ----
template<int T>
__device__ __forceinline__ void p1_all(
    float4& m0, float4& m1, float4& m2, float4& m3,
    const float* __restrict__ sm, int g7, float* __restrict__ dst,
    bool isL, bool isR)
{
    if constexpr (T < 12) {
        if constexpr (T == 0) {
            m0 = ldrow4s(sm, g7 + bofs(0) - 1);
            m1 = ldrow4s(sm, g7 + bofs(0)    );
            m2 = ldrow4s(sm, g7 + bofs(0) + 1);
            m3 = ldrow4s(sm, g7 + bofs(0) + 2);
        } else if constexpr (bofs(T) != bofs(T - 1)) {   // advances by <=1
            m0 = m1; m1 = m2; m2 = m3;
            m3 = ldrow4s(sm, g7 + bofs(T) + 2);
        }
        constexpr float W0 = wgt(T, 0), W1 = wgt(T, 1), W2 = wgt(T, 2), W3 = wgt(T, 3);
        float4 v;
        v.x = fmaf(m3.x, W3, fmaf(m2.x, W2, fmaf(m1.x, W1, m0.x * W0)));
        v.y = fmaf(m3.y, W3, fmaf(m2.y, W2, fmaf(m1.y, W1, m0.y * W0)));
        v.z = fmaf(m3.z, W3, fmaf(m2.z, W2, fmaf(m1.z, W1, m0.z * W0)));
        v.w = fmaf(m3.w, W3, fmaf(m2.w, W2, fmaf(m1.w, W1, m0.w * W0)));
        *(float4*)(dst + T * TS) = v;
        if (isL) *(float2*)(dst + T * TS - 2) = make_float2(v.x, v.x); // cols -2,-1
        if (isR) *(float2*)(dst + T * TS + 4) = make_float2(v.w, v.w); // cols 56,57
        p1_all<T + 1>(m0, m1, m2, m3, sm, g7, dst, isL, isR);
    }
}

// ---------------- pass 2 helpers ----------------
template<int C, int HI>
__device__ __forceinline__ void p2chunks(float* __restrict__ row, const float4* __restrict__ src) {
    if constexpr (C <= HI) {
        float4 q = src[C];
        row[4 * C + 0] = q.x; row[4 * C + 1] = q.y;
        row[4 * C + 2] = q.z; row[4 * C + 3] = q.w;
        p2chunks<C + 1, HI>(row, src);
    }
}
template<int T>
__device__ __forceinline__ void p2load(float* __restrict__ row, const float4* __restrict__ src) {
    constexpr int hi = (brel(T) + 6) / 4;
    constexpr int lo = (T == 0) ? 0 : (brel(T - 1) + 6) / 4 + 1;
    p2chunks<lo, hi>(row, src);
}
template<int T>
__device__ __forceinline__ float p2v(const float* __restrict__ row) {
    constexpr int   t = T % 12;
    constexpr int   b = brel(T) + 3;
    constexpr float W0 = wgt(t, 0), W1 = wgt(t, 1), W2 = wgt(t, 2), W3 = wgt(t, 3);
    return fmaf(row[b + 3], W3, fmaf(row[b + 2], W2, fmaf(row[b + 1], W1, row[b] * W0)));
}
template<int G>
__device__ __forceinline__ void p2group(
    float* __restrict__ row, const float4* __restrict__ src,
    float& best, int& bestGS, int baseIdx)
{
    if constexpr (G < 12) {
        p2load<4 * G + 0>(row, src); float v0 = p2v<4 * G + 0>(row);
        p2load<4 * G + 1>(row, src); float v1 = p2v<4 * G + 1>(row);
        p2load<4 * G + 2>(row, src); float v2 = p2v<4 * G + 2>(row);
        p2load<4 * G + 3>(row, src); float v3 = p2v<4 * G + 3>(row);
        float gm = fmaxf(fmaxf(v0, v1), fmaxf(v2, v3));
        if (gm > best) { best = gm; bestGS = baseIdx + 4 * G; } // strict '>': earliest group
        p2group<G + 1>(row, src, best, bestGS, baseIdx);
    }
}

__global__ __launch_bounds__(NT) void kp_kernel(
    const float* __restrict__ masks,
    const float* __restrict__ boxes,
    float* __restrict__ out)
{
    __shared__ float s_mask[HIN * HIN];    // 12.25 KB (cp.async staged)
    __shared__ float s_tmp[OUT * TS];      // 26.1 KB (stride 68)
    __shared__ float s_rv[NT / 32];
    __shared__ int   s_ri[NT / 32];

    const int tid  = threadIdx.x;
    const int map0 = blockIdx.x * MPC;

    unsigned int smask_u = (unsigned int)__cvta_generic_to_shared(s_mask);

    // prologue: prefetch map0's mask (784 float4 = 12.25 KB)
    {
        const float4* g = (const float4*)(masks + (size_t)map0 * (HIN * HIN));
        #pragma unroll
        for (int i = 0; i < 4; i++)
            cp16(smask_u + (tid + i * NT) * 16, g + tid + i * NT);
        if (tid < 16)
            cp16(smask_u + (768 + tid) * 16, g + 768 + tid);
        cp_commit();
    }

    for (int m = 0; m < MPC; m++) {
        const int map = map0 + m;

        cp_wait0();
        __syncthreads();    // mask visible to all; protects s_tmp/s_rv reuse

        // ---- pass 1: 112 threads, (row-block g, column quad q), smem->smem ----
        if (tid < 112) {
            int g = tid / 14;          // 0..7 : 12 output rows each
            int q = tid - g * 14;      // 0..13: cols 4q..4q+3
            const float* sm = s_mask + 4 * q;
            float* dst = s_tmp + (12 * g) * TS + PAD + 4 * q;
            float4 m0, m1, m2, m3;
            p1_all<0>(m0, m1, m2, m3, sm, 7 * g, dst, q == 0, q == 13);
        }
        __syncthreads();

        // ---- prefetch next map's mask (overlaps pass 2) ----
        if (m + 1 < MPC) {
            const float4* g = (const float4*)(masks + (size_t)(map + 1) * (HIN * HIN));
            #pragma unroll
            for (int i = 0; i < 4; i++)
                cp16(smask_u + (tid + i * NT) * 16, g + tid + i * NT);
            if (tid < 16)
                cp16(smask_u + (768 + tid) * 16, g + 768 + tid);
        }
        cp_commit();

        // ---- pass 2: horizontal 56->96 with grouped argmax ----
        float best = -FLT_MAX;
        int bestGS = 0x7fffffff;
        {
            int h    = tid >> 1;
            int half = tid & 1;
            const float4* src = (const float4*)(s_tmp + h * TS + 28 * half);
            float row[36];
            p2group<0>(row, src, best, bestGS, h * OUT + 48 * half);
        }

        #pragma unroll
        for (int off = 16; off > 0; off >>= 1) {
            float ov = __shfl_down_sync(0xffffffffu, best, off);
            int   og = __shfl_down_sync(0xffffffffu, bestGS, off);
            if (ov > best || (ov == best && og < bestGS)) { best = ov; bestGS = og; }
        }
        if ((tid & 31) == 0) { s_rv[tid >> 5] = best; s_ri[tid >> 5] = bestGS; }
        __syncthreads();

        if (tid == 0) {
            #pragma unroll
            for (int i = 1; i < NT / 32; i++) {
                float ov = s_rv[i]; int og = s_ri[i];
                if (ov > best || (ov == best && og < bestGS)) { best = ov; bestGS = og; }
            }
            // exact within-group index recovery (bit-identical recompute)
            int gs = bestGS;
            int hh = gs / OUT;
            int w0 = gs - hh * OUT;
            int found = 0;
            #pragma unroll
            for (int i = 3; i >= 0; i--) {    // descending: final 'found' = first match
                int T = w0 + i;
                int d = T / 12;
                int t = T - 12 * d;
                const float* p = s_tmp + hh * TS + 7 * d + cWT.b[t] + 3;
                float v = fmaf(p[3], cWT.w[t][3],
                          fmaf(p[2], cWT.w[t][2],
                          fmaf(p[1], cWT.w[t][1], p[0] * cWT.w[t][0])));
                if (v == best) { found = i; }
            }
            int bestIdx = gs + found;

            int r = map / K_;
            int k = map - r * K_;
            float b0 = boxes[r * 4 + 0];
            float b1 = boxes[r * 4 + 1];
            float b2 = boxes[r * 4 + 2];
            float b3 = boxes[r * 4 + 3];
            float len0 = fmaxf(b2 - b0, 1.0f);
            float len1 = fmaxf(b3 - b1, 1.0f);
            int y = bestIdx / OUT;
            int x = bestIdx - y * OUT;
            float p0 = ((float)y + 0.5f) * (len0 / (float)OUT) + b0;
            float p1 = ((float)x + 0.5f) * (len1 / (float)OUT) + b1;

            float* pred   = out;                    // [R, 3, K]
            float* scores = out + R_ * 3 * K_;      // [R, K]
            pred[r * 3 * K_ + 0 * K_ + k] = p0;
            pred[r * 3 * K_ + 1 * K_ + k] = p1;
            pred[r * 3 * K_ + 2 * K_ + k] = 1.0f;
            scores[r * K_ + k] = best;
        }
    }
}

extern "C" void kernel_launch(void* const* d_in, const int* in_sizes, int n_in,
                              void* d_out, int out_size) {
    const float* masks = (const float*)d_in[0];   // [512,17,56,56] f32
    const float* boxes = (const float*)d_in[1];   // [512,4] f32
    float* out = (float*)d_out;
    kp_kernel<<<NMAP / MPC, NT>>>(masks, boxes, out);
}